// round 1
// baseline (speedup 1.0000x reference)
#include <cuda_runtime.h>
#include <stdint.h>

#define NN 100000
#define EE 3200000
#define INC 495
#define HC 16

// ---------------- static device scratch (no allocations allowed) ----------------
__device__ __align__(16) float g_deg[NN];
__device__ __align__(16) float g_dis[NN];
__device__ int   g_src[EE];
__device__ int   g_dst[EE];
__device__ __align__(16) float g_T[NN * HC];   // pre-aggregation t = h@W ; later reused as head "A"
__device__ __align__(16) float g_H[NN * HC];   // aggregated layer output (pre-relu)
__device__ __align__(16) float g_B[NN * HC];   // head "B"
__device__ int   g_is64;                       // edge_index dtype flag

// ---------------- small utility kernels ----------------
__global__ void k_set_deg() {
    int i = blockIdx.x * blockDim.x + threadIdx.x;
    if (i < NN) g_deg[i] = 1.0f;               // self-loop
}

// Detect whether edge_index arrived as int64 or int32.
// Values are in [0, 100000). If int64 (little-endian), every odd 32-bit word is 0.
__global__ void k_detect(const unsigned int* __restrict__ w) {
    __shared__ unsigned int s_or;
    if (threadIdx.x == 0) s_or = 0u;
    __syncthreads();
    unsigned int v = 0u;
    // scan odd words of the first 8192 words
    for (int i = threadIdx.x; i < 4096; i += blockDim.x)
        v |= w[2 * i + 1];
    atomicOr(&s_or, v);
    __syncthreads();
    if (threadIdx.x == 0) g_is64 = (s_or == 0u) ? 1 : 0;
}

__global__ void k_edge_prep(const void* __restrict__ ei_raw) {
    int e = blockIdx.x * blockDim.x + threadIdx.x;
    if (e >= EE) return;
    int s, d;
    if (g_is64) {
        const long long* ei = (const long long*)ei_raw;
        s = (int)ei[e];
        d = (int)ei[EE + e];
    } else {
        const int* ei = (const int*)ei_raw;
        s = ei[e];
        d = ei[EE + e];
    }
    g_src[e] = s;
    g_dst[e] = d;
    atomicAdd(&g_deg[d], 1.0f);                // exact: integer-valued fp32 sums
}

__global__ void k_dis() {
    int i = blockIdx.x * blockDim.x + threadIdx.x;
    if (i < NN) g_dis[i] = rsqrtf(g_deg[i]);
}

// ---------------- layer 0 dense: t = x @ W0 ; H = t*dis^2 + b0 ----------------
// warp handles 4 rows; W0 staged in padded shared memory (conflict-free, stride 17)
__global__ __launch_bounds__(256) void k_dense0(const float* __restrict__ x,
                                                const float* __restrict__ W0,
                                                const float* __restrict__ b0) {
    __shared__ float sW[INC * 17];
    for (int idx = threadIdx.x; idx < INC * HC; idx += 256) {
        int c = idx >> 4, j = idx & 15;
        sW[c * 17 + j] = W0[idx];
    }
    __syncthreads();

    int warp = threadIdx.x >> 5;
    int lane = threadIdx.x & 31;
    int r0 = (blockIdx.x * 8 + warp) * 4;
    if (r0 >= NN) return;

    float acc[4][16];
#pragma unroll
    for (int i = 0; i < 4; i++)
#pragma unroll
        for (int j = 0; j < 16; j++) acc[i][j] = 0.0f;

    for (int c = lane; c < INC; c += 32) {
        float xv[4];
#pragma unroll
        for (int i = 0; i < 4; i++) {
            int r = r0 + i;
            xv[i] = (r < NN) ? __ldg(&x[(size_t)r * INC + c]) : 0.0f;
        }
#pragma unroll
        for (int j = 0; j < 16; j++) {
            float w = sW[c * 17 + j];
#pragma unroll
            for (int i = 0; i < 4; i++) acc[i][j] = fmaf(xv[i], w, acc[i][j]);
        }
    }

#pragma unroll
    for (int j = 0; j < 16; j++) {
#pragma unroll
        for (int i = 0; i < 4; i++) {
            float v = acc[i][j];
            v += __shfl_xor_sync(0xffffffffu, v, 16);
            v += __shfl_xor_sync(0xffffffffu, v, 8);
            v += __shfl_xor_sync(0xffffffffu, v, 4);
            v += __shfl_xor_sync(0xffffffffu, v, 2);
            v += __shfl_xor_sync(0xffffffffu, v, 1);
            if (lane == j) {
                int r = r0 + i;
                if (r < NN) {
                    float ds = g_dis[r];
                    g_T[r * 16 + j] = v;
                    g_H[r * 16 + j] = fmaf(v, ds * ds, __ldg(&b0[j]));
                }
            }
        }
    }
}

// ---------------- scatter: H[dst] += norm * T[src]  (vector RED to L2) ----------------
__global__ __launch_bounds__(256) void k_scatter() {
    int e = blockIdx.x * blockDim.x + threadIdx.x;
    if (e >= EE) return;
    int s = g_src[e];
    int d = g_dst[e];
    float nv = __ldg(&g_dis[s]) * __ldg(&g_dis[d]);
    const float4* ts = (const float4*)(g_T + (size_t)s * 16);
    unsigned long long gp =
        (unsigned long long)__cvta_generic_to_global(g_H + (size_t)d * 16);
#pragma unroll
    for (int q = 0; q < 4; q++) {
        float4 v = __ldg(&ts[q]);
        asm volatile("red.global.add.v4.f32 [%0], {%1,%2,%3,%4};"
                     :: "l"(gp + (unsigned long long)q * 16),
                        "f"(v.x * nv), "f"(v.y * nv), "f"(v.z * nv), "f"(v.w * nv)
                     : "memory");
    }
}

// ---------------- layers 1,2 dense: t = relu(H) @ W ; H = t*dis^2 + b ----------------
__global__ __launch_bounds__(256) void k_dense16(const float* __restrict__ W,
                                                 const float* __restrict__ b) {
    __shared__ float sW[256];
    __shared__ float sb[16];
    sW[threadIdx.x] = W[threadIdx.x];
    if (threadIdx.x < 16) sb[threadIdx.x] = b[threadIdx.x];
    __syncthreads();

    int i = blockIdx.x * blockDim.x + threadIdx.x;
    if (i >= NN) return;

    float h[16];
    const float4* hp = (const float4*)(g_H + (size_t)i * 16);
#pragma unroll
    for (int q = 0; q < 4; q++) {
        float4 v = hp[q];
        h[q * 4 + 0] = fmaxf(v.x, 0.0f);
        h[q * 4 + 1] = fmaxf(v.y, 0.0f);
        h[q * 4 + 2] = fmaxf(v.z, 0.0f);
        h[q * 4 + 3] = fmaxf(v.w, 0.0f);
    }
    float o[16];
#pragma unroll
    for (int j = 0; j < 16; j++) {
        float a = 0.0f;
#pragma unroll
        for (int k = 0; k < 16; k++) a = fmaf(h[k], sW[k * 16 + j], a);
        o[j] = a;
    }
    float ds = g_dis[i];
    float d2 = ds * ds;
    float4* tp = (float4*)(g_T + (size_t)i * 16);
    float4* ho = (float4*)(g_H + (size_t)i * 16);
#pragma unroll
    for (int q = 0; q < 4; q++) {
        tp[q] = make_float4(o[q * 4 + 0], o[q * 4 + 1], o[q * 4 + 2], o[q * 4 + 3]);
        ho[q] = make_float4(fmaf(o[q * 4 + 0], d2, sb[q * 4 + 0]),
                            fmaf(o[q * 4 + 1], d2, sb[q * 4 + 1]),
                            fmaf(o[q * 4 + 2], d2, sb[q * 4 + 2]),
                            fmaf(o[q * 4 + 3], d2, sb[q * 4 + 3]));
    }
}

// ---------------- head precompute: A = relu(h)@Wf0[0:16] + bf0 ; B = relu(h)@Wf0[16:32] ----------------
__global__ __launch_bounds__(256) void k_head(const float* __restrict__ Wf0,
                                              const float* __restrict__ bf0) {
    __shared__ float sW[512];
    __shared__ float sb[16];
    for (int idx = threadIdx.x; idx < 512; idx += 256) sW[idx] = Wf0[idx];
    if (threadIdx.x < 16) sb[threadIdx.x] = bf0[threadIdx.x];
    __syncthreads();

    int i = blockIdx.x * blockDim.x + threadIdx.x;
    if (i >= NN) return;

    float h[16];
    const float4* hp = (const float4*)(g_H + (size_t)i * 16);
#pragma unroll
    for (int q = 0; q < 4; q++) {
        float4 v = hp[q];
        h[q * 4 + 0] = fmaxf(v.x, 0.0f);
        h[q * 4 + 1] = fmaxf(v.y, 0.0f);
        h[q * 4 + 2] = fmaxf(v.z, 0.0f);
        h[q * 4 + 3] = fmaxf(v.w, 0.0f);
    }
    float a[16], bb[16];
#pragma unroll
    for (int j = 0; j < 16; j++) { a[j] = sb[j]; bb[j] = 0.0f; }
#pragma unroll
    for (int k = 0; k < 16; k++) {
        float hv = h[k];
#pragma unroll
        for (int j = 0; j < 16; j++) {
            a[j]  = fmaf(hv, sW[k * 16 + j], a[j]);
            bb[j] = fmaf(hv, sW[(16 + k) * 16 + j], bb[j]);
        }
    }
    float4* ap = (float4*)(g_T + (size_t)i * 16);
    float4* bp = (float4*)(g_B + (size_t)i * 16);
#pragma unroll
    for (int q = 0; q < 4; q++) {
        ap[q] = make_float4(a[q * 4 + 0], a[q * 4 + 1], a[q * 4 + 2], a[q * 4 + 3]);
        bp[q] = make_float4(bb[q * 4 + 0], bb[q * 4 + 1], bb[q * 4 + 2], bb[q * 4 + 3]);
    }
}

// ---------------- final per-edge output: out = relu(A[s]+B[d]) . Wf1 + bf1 ----------------
__global__ __launch_bounds__(256) void k_edge_out(const float* __restrict__ Wf1,
                                                  const float* __restrict__ bf1,
                                                  float* __restrict__ out) {
    __shared__ float sW[16];
    __shared__ float sb1;
    if (threadIdx.x < 16) sW[threadIdx.x] = Wf1[threadIdx.x];
    if (threadIdx.x == 0) sb1 = bf1[0];
    __syncthreads();

    int e = blockIdx.x * blockDim.x + threadIdx.x;
    if (e >= EE) return;
    int s = g_src[e];
    int d = g_dst[e];
    const float4* ap = (const float4*)(g_T + (size_t)s * 16);
    const float4* bp = (const float4*)(g_B + (size_t)d * 16);
    float sum = sb1;
#pragma unroll
    for (int q = 0; q < 4; q++) {
        float4 av = __ldg(&ap[q]);
        float4 bv = __ldg(&bp[q]);
        sum = fmaf(fmaxf(av.x + bv.x, 0.0f), sW[q * 4 + 0], sum);
        sum = fmaf(fmaxf(av.y + bv.y, 0.0f), sW[q * 4 + 1], sum);
        sum = fmaf(fmaxf(av.z + bv.z, 0.0f), sW[q * 4 + 2], sum);
        sum = fmaf(fmaxf(av.w + bv.w, 0.0f), sW[q * 4 + 3], sum);
    }
    out[e] = sum;
}

// ---------------- launch ----------------
extern "C" void kernel_launch(void* const* d_in, const int* in_sizes, int n_in,
                              void* d_out, int out_size) {
    const float* x   = (const float*)d_in[0];
    const void*  ei  = d_in[1];
    const float* W0  = (const float*)d_in[2];
    const float* b0  = (const float*)d_in[3];
    const float* W1  = (const float*)d_in[4];
    const float* b1  = (const float*)d_in[5];
    const float* W2  = (const float*)d_in[6];
    const float* b2  = (const float*)d_in[7];
    const float* Wf0 = (const float*)d_in[8];
    const float* bf0 = (const float*)d_in[9];
    const float* Wf1 = (const float*)d_in[10];
    const float* bf1 = (const float*)d_in[11];
    float* out = (float*)d_out;

    const int TB = 256;
    const int gN = (NN + TB - 1) / TB;          // 391
    const int gE = (EE + TB - 1) / TB;          // 12500
    const int gD0 = (NN + 31) / 32;             // 3125 (32 rows/block)

    k_set_deg<<<gN, TB>>>();
    k_detect<<<1, 256>>>((const unsigned int*)ei);
    k_edge_prep<<<gE, TB>>>(ei);
    k_dis<<<gN, TB>>>();

    // layer 0
    k_dense0<<<gD0, TB>>>(x, W0, b0);
    k_scatter<<<gE, TB>>>();
    // layer 1
    k_dense16<<<gN, TB>>>(W1, b1);
    k_scatter<<<gE, TB>>>();
    // layer 2
    k_dense16<<<gN, TB>>>(W2, b2);
    k_scatter<<<gE, TB>>>();
    // edge head
    k_head<<<gN, TB>>>(Wf0, bf0);
    k_edge_out<<<gE, TB>>>(Wf1, bf1, out);
}

// round 3
// speedup vs baseline: 1.1665x; 1.1665x over previous
#include <cuda_runtime.h>
#include <stdint.h>

#define NN 100000
#define EE 3200000
#define INC 495
#define HC 16

// ---------------- static device scratch ----------------
__device__ __align__(16) float g_dis[NN];
__device__ int   g_cnt[NN];          // in-degree counts (excl self-loop)
__device__ int   g_off[NN + 1];      // CSR row offsets
__device__ int   g_cur[NN];          // fill cursors
__device__ int   g_csr[EE];          // incoming src list per dst
__device__ int   g_src[EE];
__device__ int   g_dst[EE];
__device__ __align__(16) float g_T[NN * HC];   // T' = (h@W)*dis ; later head "A"
__device__ __align__(16) float g_H[NN * HC];   // aggregated pre-relu output
__device__ __align__(16) float g_B[NN * HC];   // head "B"
__device__ int   g_is64;

// ---------------- utility kernels ----------------
__global__ __launch_bounds__(256) void k_zero_cnt() {
    int i = blockIdx.x * blockDim.x + threadIdx.x;
    if (i < NN) g_cnt[i] = 0;
}

// int64 vs int32 detection: values < 2^32, so int64 => all odd 32-bit words zero
__global__ __launch_bounds__(256) void k_detect(const unsigned int* __restrict__ w) {
    __shared__ unsigned int s_or;
    if (threadIdx.x == 0) s_or = 0u;
    __syncthreads();
    unsigned int v = 0u;
    for (int i = threadIdx.x; i < 4096; i += blockDim.x)
        v |= w[2 * i + 1];
    atomicOr(&s_or, v);
    __syncthreads();
    if (threadIdx.x == 0) g_is64 = (s_or == 0u) ? 1 : 0;
}

__global__ __launch_bounds__(256) void k_edge_prep(const void* __restrict__ ei_raw) {
    int e = blockIdx.x * blockDim.x + threadIdx.x;
    if (e >= EE) return;
    int s, d;
    if (g_is64) {
        const long long* ei = (const long long*)ei_raw;
        s = (int)ei[e];
        d = (int)ei[EE + e];
    } else {
        const int* ei = (const int*)ei_raw;
        s = ei[e];
        d = ei[EE + e];
    }
    g_src[e] = s;
    g_dst[e] = d;
    atomicAdd(&g_cnt[d], 1);
}

// single-block exclusive scan of g_cnt -> g_off
__global__ __launch_bounds__(1024) void k_scan() {
    __shared__ int s_part[1024];
    const int CH = (NN + 1023) / 1024;   // 98
    int t = threadIdx.x;
    int base = t * CH;
    int sum = 0;
    for (int k = 0; k < CH; k++) {
        int i = base + k;
        if (i < NN) sum += g_cnt[i];
    }
    s_part[t] = sum;
    __syncthreads();
    for (int off = 1; off < 1024; off <<= 1) {
        int v = (t >= off) ? s_part[t - off] : 0;
        __syncthreads();
        s_part[t] += v;
        __syncthreads();
    }
    int run = (t == 0) ? 0 : s_part[t - 1];
    for (int k = 0; k < CH; k++) {
        int i = base + k;
        if (i < NN) { g_off[i] = run; run += g_cnt[i]; }
    }
    if (t == 1023) g_off[NN] = EE;
}

__global__ __launch_bounds__(256) void k_dis_cur() {
    int i = blockIdx.x * blockDim.x + threadIdx.x;
    if (i < NN) {
        g_dis[i] = rsqrtf((float)(g_cnt[i] + 1));  // +1 self-loop
        g_cur[i] = g_off[i];
    }
}

__global__ __launch_bounds__(256) void k_fill() {
    int e = blockIdx.x * blockDim.x + threadIdx.x;
    if (e >= EE) return;
    int d = g_dst[e];
    int pos = atomicAdd(&g_cur[d], 1);
    g_csr[pos] = g_src[e];
}

// ---------------- layer 0 dense: T' = (x @ W0) * dis ----------------
__global__ __launch_bounds__(256) void k_dense0(const float* __restrict__ x,
                                                const float* __restrict__ W0) {
    __shared__ float sW[INC * 17];
    for (int idx = threadIdx.x; idx < INC * HC; idx += 256) {
        int c = idx >> 4, j = idx & 15;
        sW[c * 17 + j] = W0[idx];
    }
    __syncthreads();

    int warp = threadIdx.x >> 5;
    int lane = threadIdx.x & 31;
    int r0 = (blockIdx.x * 8 + warp) * 4;
    if (r0 >= NN) return;

    float acc[4][16];
#pragma unroll
    for (int i = 0; i < 4; i++)
#pragma unroll
        for (int j = 0; j < 16; j++) acc[i][j] = 0.0f;

    for (int c = lane; c < INC; c += 32) {
        float xv[4];
#pragma unroll
        for (int i = 0; i < 4; i++) {
            int r = r0 + i;
            xv[i] = (r < NN) ? __ldg(&x[(size_t)r * INC + c]) : 0.0f;
        }
#pragma unroll
        for (int j = 0; j < 16; j++) {
            float w = sW[c * 17 + j];
#pragma unroll
            for (int i = 0; i < 4; i++) acc[i][j] = fmaf(xv[i], w, acc[i][j]);
        }
    }

#pragma unroll
    for (int j = 0; j < 16; j++) {
#pragma unroll
        for (int i = 0; i < 4; i++) {
            float v = acc[i][j];
            v += __shfl_xor_sync(0xffffffffu, v, 16);
            v += __shfl_xor_sync(0xffffffffu, v, 8);
            v += __shfl_xor_sync(0xffffffffu, v, 4);
            v += __shfl_xor_sync(0xffffffffu, v, 2);
            v += __shfl_xor_sync(0xffffffffu, v, 1);
            if (lane == j) {
                int r = r0 + i;
                if (r < NN) g_T[r * 16 + j] = v * g_dis[r];
            }
        }
    }
}

// ---------------- CSR aggregation: H[d] = dis[d]*(sum T'[src] + T'[d]) + b ----------------
// one warp per node; lanes 0-15 even edges, 16-31 odd edges, one channel each
__global__ __launch_bounds__(256) void k_agg(const float* __restrict__ b) {
    int i = (blockIdx.x * blockDim.x + threadIdx.x) >> 5;
    if (i >= NN) return;
    int lane = threadIdx.x & 31;
    int j = lane & 15;
    int half = lane >> 4;
    int beg = g_off[i];
    int end = g_off[i + 1];
    float acc = 0.0f;
    for (int e = beg + half; e < end; e += 2) {
        int s = g_csr[e];
        acc += __ldg(&g_T[s * 16 + j]);
    }
    acc += __shfl_xor_sync(0xffffffffu, acc, 16);
    if (lane < 16) {
        acc += g_T[i * 16 + j];                    // self-loop T'
        g_H[i * 16 + j] = fmaf(g_dis[i], acc, __ldg(&b[j]));
    }
}

// ---------------- layers 1,2 dense: T' = (relu(H) @ W) * dis ----------------
__global__ __launch_bounds__(256) void k_dense16(const float* __restrict__ W) {
    __shared__ float sW[256];
    sW[threadIdx.x] = W[threadIdx.x];
    __syncthreads();

    int i = blockIdx.x * blockDim.x + threadIdx.x;
    if (i >= NN) return;

    float h[16];
    const float4* hp = (const float4*)(g_H + (size_t)i * 16);
#pragma unroll
    for (int q = 0; q < 4; q++) {
        float4 v = hp[q];
        h[q * 4 + 0] = fmaxf(v.x, 0.0f);
        h[q * 4 + 1] = fmaxf(v.y, 0.0f);
        h[q * 4 + 2] = fmaxf(v.z, 0.0f);
        h[q * 4 + 3] = fmaxf(v.w, 0.0f);
    }
    float o[16];
#pragma unroll
    for (int j = 0; j < 16; j++) {
        float a = 0.0f;
#pragma unroll
        for (int k = 0; k < 16; k++) a = fmaf(h[k], sW[k * 16 + j], a);
        o[j] = a;
    }
    float ds = g_dis[i];
    float4* tp = (float4*)(g_T + (size_t)i * 16);
#pragma unroll
    for (int q = 0; q < 4; q++)
        tp[q] = make_float4(o[q * 4 + 0] * ds, o[q * 4 + 1] * ds,
                            o[q * 4 + 2] * ds, o[q * 4 + 3] * ds);
}

// ---------------- head precompute: A = relu(h)@Wf0_top + bf0 ; B = relu(h)@Wf0_bot ----------------
__global__ __launch_bounds__(256) void k_head(const float* __restrict__ Wf0,
                                              const float* __restrict__ bf0) {
    __shared__ float sW[512];
    __shared__ float sb[16];
    for (int idx = threadIdx.x; idx < 512; idx += 256) sW[idx] = Wf0[idx];
    if (threadIdx.x < 16) sb[threadIdx.x] = bf0[threadIdx.x];
    __syncthreads();

    int i = blockIdx.x * blockDim.x + threadIdx.x;
    if (i >= NN) return;

    float h[16];
    const float4* hp = (const float4*)(g_H + (size_t)i * 16);
#pragma unroll
    for (int q = 0; q < 4; q++) {
        float4 v = hp[q];
        h[q * 4 + 0] = fmaxf(v.x, 0.0f);
        h[q * 4 + 1] = fmaxf(v.y, 0.0f);
        h[q * 4 + 2] = fmaxf(v.z, 0.0f);
        h[q * 4 + 3] = fmaxf(v.w, 0.0f);
    }
    float a[16], bb[16];
#pragma unroll
    for (int j = 0; j < 16; j++) { a[j] = sb[j]; bb[j] = 0.0f; }
#pragma unroll
    for (int k = 0; k < 16; k++) {
        float hv = h[k];
#pragma unroll
        for (int j = 0; j < 16; j++) {
            a[j]  = fmaf(hv, sW[k * 16 + j], a[j]);
            bb[j] = fmaf(hv, sW[(16 + k) * 16 + j], bb[j]);
        }
    }
    float4* ap = (float4*)(g_T + (size_t)i * 16);
    float4* bp = (float4*)(g_B + (size_t)i * 16);
#pragma unroll
    for (int q = 0; q < 4; q++) {
        ap[q] = make_float4(a[q * 4 + 0], a[q * 4 + 1], a[q * 4 + 2], a[q * 4 + 3]);
        bp[q] = make_float4(bb[q * 4 + 0], bb[q * 4 + 1], bb[q * 4 + 2], bb[q * 4 + 3]);
    }
}

// ---------------- final per-edge output ----------------
__global__ __launch_bounds__(256) void k_edge_out(const float* __restrict__ Wf1,
                                                  const float* __restrict__ bf1,
                                                  float* __restrict__ out) {
    __shared__ float sW[16];
    __shared__ float sb1;
    if (threadIdx.x < 16) sW[threadIdx.x] = Wf1[threadIdx.x];
    if (threadIdx.x == 0) sb1 = bf1[0];
    __syncthreads();

    int e = blockIdx.x * blockDim.x + threadIdx.x;
    if (e >= EE) return;
    int s = g_src[e];
    int d = g_dst[e];
    const float4* ap = (const float4*)(g_T + (size_t)s * 16);
    const float4* bp = (const float4*)(g_B + (size_t)d * 16);
    float sum = sb1;
#pragma unroll
    for (int q = 0; q < 4; q++) {
        float4 av = __ldg(&ap[q]);
        float4 bv = __ldg(&bp[q]);
        sum = fmaf(fmaxf(av.x + bv.x, 0.0f), sW[q * 4 + 0], sum);
        sum = fmaf(fmaxf(av.y + bv.y, 0.0f), sW[q * 4 + 1], sum);
        sum = fmaf(fmaxf(av.z + bv.z, 0.0f), sW[q * 4 + 2], sum);
        sum = fmaf(fmaxf(av.w + bv.w, 0.0f), sW[q * 4 + 3], sum);
    }
    out[e] = sum;
}

// ---------------- launch ----------------
extern "C" void kernel_launch(void* const* d_in, const int* in_sizes, int n_in,
                              void* d_out, int out_size) {
    const float* x   = (const float*)d_in[0];
    const void*  ei  = d_in[1];
    const float* W0  = (const float*)d_in[2];
    const float* b0  = (const float*)d_in[3];
    const float* W1  = (const float*)d_in[4];
    const float* b1  = (const float*)d_in[5];
    const float* W2  = (const float*)d_in[6];
    const float* b2  = (const float*)d_in[7];
    const float* Wf0 = (const float*)d_in[8];
    const float* bf0 = (const float*)d_in[9];
    const float* Wf1 = (const float*)d_in[10];
    const float* bf1 = (const float*)d_in[11];
    float* out = (float*)d_out;

    const int TB = 256;
    const int gN = (NN + TB - 1) / TB;          // 391
    const int gE = (EE + TB - 1) / TB;          // 12500
    const int gD0 = (NN + 31) / 32;             // 3125
    const int gW = (NN * 32 + TB - 1) / TB;     // 12500 (warp per node)

    // CSR build
    k_zero_cnt<<<gN, TB>>>();
    k_detect<<<1, 256>>>((const unsigned int*)ei);
    k_edge_prep<<<gE, TB>>>(ei);
    k_scan<<<1, 1024>>>();
    k_dis_cur<<<gN, TB>>>();
    k_fill<<<gE, TB>>>();

    // layer 0
    k_dense0<<<gD0, TB>>>(x, W0);
    k_agg<<<gW, TB>>>(b0);
    // layer 1
    k_dense16<<<gN, TB>>>(W1);
    k_agg<<<gW, TB>>>(b1);
    // layer 2
    k_dense16<<<gN, TB>>>(W2);
    k_agg<<<gW, TB>>>(b2);
    // edge head
    k_head<<<gN, TB>>>(Wf0, bf0);
    k_edge_out<<<gE, TB>>>(Wf1, bf1, out);
}

// round 4
// speedup vs baseline: 1.3941x; 1.1951x over previous
#include <cuda_runtime.h>
#include <stdint.h>

#define NN 100000
#define EE 3200000
#define INC 495
#define HC 16
#define NB 391            // ceil(NN/256)

// ---------------- static device scratch ----------------
__device__ __align__(16) float g_dis[NN];
__device__ int   g_cnt[NN];          // in-degree counts (excl self-loop)
__device__ int   g_off[NN + 1];      // CSR row offsets
__device__ int   g_cur[NN];          // fill cursors
__device__ int   g_csr[EE];          // incoming src list per dst
__device__ int   g_src[EE];
__device__ int   g_dst[EE];
__device__ int   g_bsum[NB];         // per-block count sums
__device__ int   g_bpre[NB];         // exclusive prefix of block sums
__device__ __align__(16) float g_T[NN * HC];   // T' = (h@W)*dis ; later head "A"
__device__ __align__(16) float g_H[NN * HC];   // aggregated pre-relu output
__device__ __align__(16) float g_B[NN * HC];   // head "B"
__device__ int   g_is64;

// ---------------- utility kernels ----------------
__global__ __launch_bounds__(256) void k_zero_cnt() {
    int i = blockIdx.x * blockDim.x + threadIdx.x;
    if (i < NN) g_cnt[i] = 0;
}

// int64 vs int32 detection: values < 2^32, so int64 => all odd 32-bit words zero
__global__ __launch_bounds__(256) void k_detect(const unsigned int* __restrict__ w) {
    __shared__ unsigned int s_or;
    if (threadIdx.x == 0) s_or = 0u;
    __syncthreads();
    unsigned int v = 0u;
    for (int i = threadIdx.x; i < 4096; i += blockDim.x)
        v |= w[2 * i + 1];
    atomicOr(&s_or, v);
    __syncthreads();
    if (threadIdx.x == 0) g_is64 = (s_or == 0u) ? 1 : 0;
}

__global__ __launch_bounds__(256) void k_edge_prep(const void* __restrict__ ei_raw) {
    int e = blockIdx.x * blockDim.x + threadIdx.x;
    if (e >= EE) return;
    int s, d;
    if (g_is64) {
        const long long* ei = (const long long*)ei_raw;
        s = (int)ei[e];
        d = (int)ei[EE + e];
    } else {
        const int* ei = (const int*)ei_raw;
        s = ei[e];
        d = ei[EE + e];
    }
    g_src[e] = s;
    g_dst[e] = d;
    atomicAdd(&g_cnt[d], 1);
}

// ---- hierarchical scan stage 1: per-block sums of g_cnt ----
__global__ __launch_bounds__(256) void k_partial() {
    __shared__ int sh[256];
    int i = blockIdx.x * 256 + threadIdx.x;
    int v = (i < NN) ? g_cnt[i] : 0;
    sh[threadIdx.x] = v;
    __syncthreads();
#pragma unroll
    for (int off = 128; off > 0; off >>= 1) {
        if (threadIdx.x < off) sh[threadIdx.x] += sh[threadIdx.x + off];
        __syncthreads();
    }
    if (threadIdx.x == 0) g_bsum[blockIdx.x] = sh[0];
}

// ---- stage 2: single-block scan of NB block sums ----
__global__ __launch_bounds__(512) void k_scan_bsum() {
    __shared__ int sh[512];
    int t = threadIdx.x;
    sh[t] = (t < NB) ? g_bsum[t] : 0;
    __syncthreads();
#pragma unroll
    for (int off = 1; off < 512; off <<= 1) {
        int v = (t >= off) ? sh[t - off] : 0;
        __syncthreads();
        sh[t] += v;
        __syncthreads();
    }
    if (t < NB) g_bpre[t] = (t == 0) ? 0 : sh[t - 1];
}

// ---- stage 3: local exclusive scan + block prefix; fuse dis/cur init ----
__global__ __launch_bounds__(256) void k_offsets() {
    __shared__ int sh[256];
    int t = threadIdx.x;
    int i = blockIdx.x * 256 + t;
    int c = (i < NN) ? g_cnt[i] : 0;
    sh[t] = c;
    __syncthreads();
#pragma unroll
    for (int off = 1; off < 256; off <<= 1) {
        int v = (t >= off) ? sh[t - off] : 0;
        __syncthreads();
        sh[t] += v;
        __syncthreads();
    }
    if (i < NN) {
        int excl = g_bpre[blockIdx.x] + sh[t] - c;   // exclusive prefix
        g_off[i] = excl;
        g_cur[i] = excl;
        g_dis[i] = rsqrtf((float)(c + 1));           // +1 self-loop
    }
    if (i == NN - 1) g_off[NN] = EE;
}

__global__ __launch_bounds__(256) void k_fill() {
    int e = blockIdx.x * blockDim.x + threadIdx.x;
    if (e >= EE) return;
    int d = g_dst[e];
    int pos = atomicAdd(&g_cur[d], 1);
    g_csr[pos] = g_src[e];
}

// ---------------- layer 0 dense: T' = (x @ W0) * dis ----------------
__global__ __launch_bounds__(256) void k_dense0(const float* __restrict__ x,
                                                const float* __restrict__ W0) {
    __shared__ float sW[INC * 17];
    for (int idx = threadIdx.x; idx < INC * HC; idx += 256) {
        int c = idx >> 4, j = idx & 15;
        sW[c * 17 + j] = W0[idx];
    }
    __syncthreads();

    int warp = threadIdx.x >> 5;
    int lane = threadIdx.x & 31;
    int r0 = (blockIdx.x * 8 + warp) * 4;
    if (r0 >= NN) return;

    float acc[4][16];
#pragma unroll
    for (int i = 0; i < 4; i++)
#pragma unroll
        for (int j = 0; j < 16; j++) acc[i][j] = 0.0f;

    for (int c = lane; c < INC; c += 32) {
        float xv[4];
#pragma unroll
        for (int i = 0; i < 4; i++) {
            int r = r0 + i;
            xv[i] = (r < NN) ? __ldg(&x[(size_t)r * INC + c]) : 0.0f;
        }
#pragma unroll
        for (int j = 0; j < 16; j++) {
            float w = sW[c * 17 + j];
#pragma unroll
            for (int i = 0; i < 4; i++) acc[i][j] = fmaf(xv[i], w, acc[i][j]);
        }
    }

#pragma unroll
    for (int j = 0; j < 16; j++) {
#pragma unroll
        for (int i = 0; i < 4; i++) {
            float v = acc[i][j];
            v += __shfl_xor_sync(0xffffffffu, v, 16);
            v += __shfl_xor_sync(0xffffffffu, v, 8);
            v += __shfl_xor_sync(0xffffffffu, v, 4);
            v += __shfl_xor_sync(0xffffffffu, v, 2);
            v += __shfl_xor_sync(0xffffffffu, v, 1);
            if (lane == j) {
                int r = r0 + i;
                if (r < NN) g_T[r * 16 + j] = v * g_dis[r];
            }
        }
    }
}

// ---------------- CSR aggregation: H[d] = dis[d]*(sum T'[src] + T'[d]) + b ----------------
__global__ __launch_bounds__(256) void k_agg(const float* __restrict__ b) {
    int i = (blockIdx.x * blockDim.x + threadIdx.x) >> 5;
    if (i >= NN) return;
    int lane = threadIdx.x & 31;
    int j = lane & 15;
    int half = lane >> 4;
    int beg = g_off[i];
    int end = g_off[i + 1];
    float acc = 0.0f;
    for (int e = beg + half; e < end; e += 2) {
        int s = g_csr[e];
        acc += __ldg(&g_T[s * 16 + j]);
    }
    acc += __shfl_xor_sync(0xffffffffu, acc, 16);
    if (lane < 16) {
        acc += g_T[i * 16 + j];                    // self-loop T'
        g_H[i * 16 + j] = fmaf(g_dis[i], acc, __ldg(&b[j]));
    }
}

// ---------------- layers 1,2 dense: T' = (relu(H) @ W) * dis ----------------
__global__ __launch_bounds__(256) void k_dense16(const float* __restrict__ W) {
    __shared__ float sW[256];
    sW[threadIdx.x] = W[threadIdx.x];
    __syncthreads();

    int i = blockIdx.x * blockDim.x + threadIdx.x;
    if (i >= NN) return;

    float h[16];
    const float4* hp = (const float4*)(g_H + (size_t)i * 16);
#pragma unroll
    for (int q = 0; q < 4; q++) {
        float4 v = hp[q];
        h[q * 4 + 0] = fmaxf(v.x, 0.0f);
        h[q * 4 + 1] = fmaxf(v.y, 0.0f);
        h[q * 4 + 2] = fmaxf(v.z, 0.0f);
        h[q * 4 + 3] = fmaxf(v.w, 0.0f);
    }
    float o[16];
#pragma unroll
    for (int j = 0; j < 16; j++) {
        float a = 0.0f;
#pragma unroll
        for (int k = 0; k < 16; k++) a = fmaf(h[k], sW[k * 16 + j], a);
        o[j] = a;
    }
    float ds = g_dis[i];
    float4* tp = (float4*)(g_T + (size_t)i * 16);
#pragma unroll
    for (int q = 0; q < 4; q++)
        tp[q] = make_float4(o[q * 4 + 0] * ds, o[q * 4 + 1] * ds,
                            o[q * 4 + 2] * ds, o[q * 4 + 3] * ds);
}

// ---------------- head precompute ----------------
__global__ __launch_bounds__(256) void k_head(const float* __restrict__ Wf0,
                                              const float* __restrict__ bf0) {
    __shared__ float sW[512];
    __shared__ float sb[16];
    for (int idx = threadIdx.x; idx < 512; idx += 256) sW[idx] = Wf0[idx];
    if (threadIdx.x < 16) sb[threadIdx.x] = bf0[threadIdx.x];
    __syncthreads();

    int i = blockIdx.x * blockDim.x + threadIdx.x;
    if (i >= NN) return;

    float h[16];
    const float4* hp = (const float4*)(g_H + (size_t)i * 16);
#pragma unroll
    for (int q = 0; q < 4; q++) {
        float4 v = hp[q];
        h[q * 4 + 0] = fmaxf(v.x, 0.0f);
        h[q * 4 + 1] = fmaxf(v.y, 0.0f);
        h[q * 4 + 2] = fmaxf(v.z, 0.0f);
        h[q * 4 + 3] = fmaxf(v.w, 0.0f);
    }
    float a[16], bb[16];
#pragma unroll
    for (int j = 0; j < 16; j++) { a[j] = sb[j]; bb[j] = 0.0f; }
#pragma unroll
    for (int k = 0; k < 16; k++) {
        float hv = h[k];
#pragma unroll
        for (int j = 0; j < 16; j++) {
            a[j]  = fmaf(hv, sW[k * 16 + j], a[j]);
            bb[j] = fmaf(hv, sW[(16 + k) * 16 + j], bb[j]);
        }
    }
    float4* ap = (float4*)(g_T + (size_t)i * 16);
    float4* bp = (float4*)(g_B + (size_t)i * 16);
#pragma unroll
    for (int q = 0; q < 4; q++) {
        ap[q] = make_float4(a[q * 4 + 0], a[q * 4 + 1], a[q * 4 + 2], a[q * 4 + 3]);
        bp[q] = make_float4(bb[q * 4 + 0], bb[q * 4 + 1], bb[q * 4 + 2], bb[q * 4 + 3]);
    }
}

// ---------------- final per-edge output ----------------
__global__ __launch_bounds__(256) void k_edge_out(const float* __restrict__ Wf1,
                                                  const float* __restrict__ bf1,
                                                  float* __restrict__ out) {
    __shared__ float sW[16];
    __shared__ float sb1;
    if (threadIdx.x < 16) sW[threadIdx.x] = Wf1[threadIdx.x];
    if (threadIdx.x == 0) sb1 = bf1[0];
    __syncthreads();

    int e = blockIdx.x * blockDim.x + threadIdx.x;
    if (e >= EE) return;
    int s = g_src[e];
    int d = g_dst[e];
    const float4* ap = (const float4*)(g_T + (size_t)s * 16);
    const float4* bp = (const float4*)(g_B + (size_t)d * 16);
    float sum = sb1;
#pragma unroll
    for (int q = 0; q < 4; q++) {
        float4 av = __ldg(&ap[q]);
        float4 bv = __ldg(&bp[q]);
        sum = fmaf(fmaxf(av.x + bv.x, 0.0f), sW[q * 4 + 0], sum);
        sum = fmaf(fmaxf(av.y + bv.y, 0.0f), sW[q * 4 + 1], sum);
        sum = fmaf(fmaxf(av.z + bv.z, 0.0f), sW[q * 4 + 2], sum);
        sum = fmaf(fmaxf(av.w + bv.w, 0.0f), sW[q * 4 + 3], sum);
    }
    out[e] = sum;
}

// ---------------- launch ----------------
extern "C" void kernel_launch(void* const* d_in, const int* in_sizes, int n_in,
                              void* d_out, int out_size) {
    const float* x   = (const float*)d_in[0];
    const void*  ei  = d_in[1];
    const float* W0  = (const float*)d_in[2];
    const float* b0  = (const float*)d_in[3];
    const float* W1  = (const float*)d_in[4];
    const float* b1  = (const float*)d_in[5];
    const float* W2  = (const float*)d_in[6];
    const float* b2  = (const float*)d_in[7];
    const float* Wf0 = (const float*)d_in[8];
    const float* bf0 = (const float*)d_in[9];
    const float* Wf1 = (const float*)d_in[10];
    const float* bf1 = (const float*)d_in[11];
    float* out = (float*)d_out;

    const int TB = 256;
    const int gE = (EE + TB - 1) / TB;          // 12500
    const int gD0 = (NN + 31) / 32;             // 3125
    const int gW = (NN * 32 + TB - 1) / TB;     // 12500 (warp per node)
    const int gN = NB;                          // 391

    // CSR build
    k_zero_cnt<<<gN, TB>>>();
    k_detect<<<1, 256>>>((const unsigned int*)ei);
    k_edge_prep<<<gE, TB>>>(ei);
    k_partial<<<NB, TB>>>();
    k_scan_bsum<<<1, 512>>>();
    k_offsets<<<NB, TB>>>();
    k_fill<<<gE, TB>>>();

    // layer 0
    k_dense0<<<gD0, TB>>>(x, W0);
    k_agg<<<gW, TB>>>(b0);
    // layer 1
    k_dense16<<<gN, TB>>>(W1);
    k_agg<<<gW, TB>>>(b1);
    // layer 2
    k_dense16<<<gN, TB>>>(W2);
    k_agg<<<gW, TB>>>(b2);
    // edge head
    k_head<<<gN, TB>>>(Wf0, bf0);
    k_edge_out<<<gE, TB>>>(Wf1, bf1, out);
}